// round 2
// baseline (speedup 1.0000x reference)
#include <cuda_runtime.h>

#define S_    2048
#define HID_  2048
#define H_    16
#define D_    256
#define R_    64
#define RH_   32          // R/2
#define NOPE_ 192
#define QL_   1024
#define OR_   512
#define G_    4
#define EPS_  1e-6f
#define SCALE_ 0.0625f    // 256^-0.5

// ---------------- scratch (static device memory; allocation-free) ----------------
__device__ float g_cos[S_ * RH_];
__device__ float g_sin[S_ * RH_];
__device__ float g_qa[(size_t)S_ * QL_];          //  8 MB
__device__ float g_q[(size_t)S_ * H_ * D_];       // 32 MB
__device__ float g_kv[(size_t)S_ * D_];           //  2 MB
__device__ float g_scores[(size_t)H_ * S_ * S_];  // 256 MB
__device__ float g_o[(size_t)S_ * H_ * D_];       // 32 MB
__device__ float g_or[(size_t)S_ * G_ * OR_];     // 16 MB

// ---------------- block reduction helper (blockDim.x == 256) ----------------
__device__ __forceinline__ float block_reduce(float v, bool is_max) {
    __shared__ float warp_res[8];
    __shared__ float result;
    __syncthreads();   // protect shared reuse across consecutive calls
    #pragma unroll
    for (int o = 16; o; o >>= 1) {
        float other = __shfl_xor_sync(0xffffffffu, v, o);
        v = is_max ? fmaxf(v, other) : (v + other);
    }
    if ((threadIdx.x & 31) == 0) warp_res[threadIdx.x >> 5] = v;
    __syncthreads();
    if (threadIdx.x == 0) {
        int nw = (blockDim.x + 31) >> 5;
        float r = warp_res[0];
        for (int i = 1; i < nw; i++) r = is_max ? fmaxf(r, warp_res[i]) : (r + warp_res[i]);
        result = r;
    }
    __syncthreads();
    return result;
}

// ---------------- GEMM: C[M,N] = A[M,K] @ B[N,K]^T  (TN) ----------------
// 64x64 block tile, BK=16, 256 threads, 4x4 per thread.
// batch via blockIdx.z with element strides sA/sB/sC.
// causal_skip: skip block if entirely above the diagonal (square tiles).
__global__ __launch_bounds__(256) void gemm_tn(
    const float* __restrict__ A, const float* __restrict__ B, float* __restrict__ C,
    int K, int lda, int ldb, int ldc,
    long sA, long sB, long sC, int causal_skip)
{
    int row0 = blockIdx.y * 64;
    int col0 = blockIdx.x * 64;
    if (causal_skip && col0 > row0) return;
    A += (long)blockIdx.z * sA;
    B += (long)blockIdx.z * sB;
    C += (long)blockIdx.z * sC;

    __shared__ float As[16][64];
    __shared__ float Bs[16][64];
    int tid = threadIdx.x;
    int tx = tid & 15, ty = tid >> 4;
    int lm = tid >> 2;            // 0..63
    int lk = (tid & 3) << 2;      // 0,4,8,12

    const float* Ap = A + (long)(row0 + lm) * lda + lk;
    const float* Bp = B + (long)(col0 + lm) * ldb + lk;

    float acc[4][4] = {};
    for (int k0 = 0; k0 < K; k0 += 16) {
        float4 a4 = *(const float4*)(Ap + k0);
        float4 b4 = *(const float4*)(Bp + k0);
        As[lk + 0][lm] = a4.x; As[lk + 1][lm] = a4.y;
        As[lk + 2][lm] = a4.z; As[lk + 3][lm] = a4.w;
        Bs[lk + 0][lm] = b4.x; Bs[lk + 1][lm] = b4.y;
        Bs[lk + 2][lm] = b4.z; Bs[lk + 3][lm] = b4.w;
        __syncthreads();
        #pragma unroll
        for (int kk = 0; kk < 16; kk++) {
            float ra[4], rb[4];
            #pragma unroll
            for (int i = 0; i < 4; i++) ra[i] = As[kk][ty * 4 + i];
            #pragma unroll
            for (int j = 0; j < 4; j++) rb[j] = Bs[kk][tx * 4 + j];
            #pragma unroll
            for (int i = 0; i < 4; i++)
                #pragma unroll
                for (int j = 0; j < 4; j++)
                    acc[i][j] += ra[i] * rb[j];
        }
        __syncthreads();
    }
    float* Cp = C + (long)(row0 + ty * 4) * ldc + col0 + tx * 4;
    #pragma unroll
    for (int i = 0; i < 4; i++) {
        float4 v = make_float4(acc[i][0], acc[i][1], acc[i][2], acc[i][3]);
        *(float4*)(Cp + (long)i * ldc) = v;
    }
}

// ---------------- GEMM: C[M,N] = A[M,K] @ B[K,N]  (NN) ----------------
// kcap: limit K to row0+64 (causal PV).
__global__ __launch_bounds__(256) void gemm_nn(
    const float* __restrict__ A, const float* __restrict__ B, float* __restrict__ C,
    int K, int lda, int ldb, int ldc,
    long sA, long sB, long sC, int kcap)
{
    int row0 = blockIdx.y * 64;
    int col0 = blockIdx.x * 64;
    A += (long)blockIdx.z * sA;
    B += (long)blockIdx.z * sB;
    C += (long)blockIdx.z * sC;

    int Keff = kcap ? min(K, row0 + 64) : K;

    __shared__ float As[16][64];
    __shared__ float Bs[16][64];
    int tid = threadIdx.x;
    int tx = tid & 15, ty = tid >> 4;
    int lm = tid >> 2;            // 0..63  (A rows)
    int lk = (tid & 3) << 2;      // A k offset
    int bk = tid >> 4;            // 0..15  (B rows = k)
    int bn = (tid & 15) << 2;     // B col offset

    const float* Ap = A + (long)(row0 + lm) * lda + lk;
    const float* Bp = B + (long)bk * ldb + col0 + bn;

    float acc[4][4] = {};
    for (int k0 = 0; k0 < Keff; k0 += 16) {
        float4 a4 = *(const float4*)(Ap + k0);
        float4 b4 = *(const float4*)(Bp + (long)k0 * ldb);
        As[lk + 0][lm] = a4.x; As[lk + 1][lm] = a4.y;
        As[lk + 2][lm] = a4.z; As[lk + 3][lm] = a4.w;
        Bs[bk][bn + 0] = b4.x; Bs[bk][bn + 1] = b4.y;
        Bs[bk][bn + 2] = b4.z; Bs[bk][bn + 3] = b4.w;
        __syncthreads();
        #pragma unroll
        for (int kk = 0; kk < 16; kk++) {
            float ra[4], rb[4];
            #pragma unroll
            for (int i = 0; i < 4; i++) ra[i] = As[kk][ty * 4 + i];
            #pragma unroll
            for (int j = 0; j < 4; j++) rb[j] = Bs[kk][tx * 4 + j];
            #pragma unroll
            for (int i = 0; i < 4; i++)
                #pragma unroll
                for (int j = 0; j < 4; j++)
                    acc[i][j] += ra[i] * rb[j];
        }
        __syncthreads();
    }
    float* Cp = C + (long)(row0 + ty * 4) * ldc + col0 + tx * 4;
    #pragma unroll
    for (int i = 0; i < 4; i++) {
        float4 v = make_float4(acc[i][0], acc[i][1], acc[i][2], acc[i][3]);
        *(float4*)(Cp + (long)i * ldc) = v;
    }
}

// ---------------- elementwise / norm kernels ----------------
__global__ void cos_sin_k(const float* __restrict__ freqs) {
    int i = blockIdx.x * blockDim.x + threadIdx.x;
    if (i < S_ * RH_) {
        float f = freqs[i];
        g_cos[i] = cosf(f);
        g_sin[i] = sinf(f);
    }
}

// RMS-norm rows of g_qa (len QL), weight q_norm_w
__global__ __launch_bounds__(256) void rms_qa(const float* __restrict__ w) {
    int s = blockIdx.x;
    float* row = g_qa + (long)s * QL_;
    float ss = 0.f;
    for (int i = threadIdx.x; i < QL_; i += 256) { float v = row[i]; ss += v * v; }
    ss = block_reduce(ss, false);
    float sc = rsqrtf(ss / QL_ + EPS_);
    for (int i = threadIdx.x; i < QL_; i += 256) row[i] = row[i] * sc * w[i];
}

// per (s,h): normalize over D, RoPE last R dims (forward)
__global__ __launch_bounds__(256) void q_post() {
    int s = blockIdx.x, h = blockIdx.y;
    float* row = g_q + (size_t)s * (H_ * D_) + (size_t)h * D_;
    int d = threadIdx.x;
    float v = row[d];
    float ss = block_reduce(v * v, false);
    float sc = rsqrtf(ss / D_ + EPS_);
    __shared__ float sh[D_];
    sh[d] = v * sc;
    __syncthreads();
    float out;
    if (d < NOPE_) out = sh[d];
    else {
        int p = d - NOPE_, i = p >> 1;
        float c = g_cos[s * RH_ + i], sn = g_sin[s * RH_ + i];
        float x1 = sh[NOPE_ + (i << 1)], x2 = sh[NOPE_ + (i << 1) + 1];
        out = (p & 1) ? (x1 * sn + x2 * c) : (x1 * c - x2 * sn);
    }
    row[d] = out;
}

// per s: RMS over D with kv_norm_w, RoPE last R dims (forward)
__global__ __launch_bounds__(256) void kv_post(const float* __restrict__ w) {
    int s = blockIdx.x;
    float* row = g_kv + (long)s * D_;
    int d = threadIdx.x;
    float v = row[d];
    float ss = block_reduce(v * v, false);
    float sc = rsqrtf(ss / D_ + EPS_);
    __shared__ float sh[D_];
    sh[d] = v * sc * w[d];
    __syncthreads();
    float out;
    if (d < NOPE_) out = sh[d];
    else {
        int p = d - NOPE_, i = p >> 1;
        float c = g_cos[s * RH_ + i], sn = g_sin[s * RH_ + i];
        float x1 = sh[NOPE_ + (i << 1)], x2 = sh[NOPE_ + (i << 1) + 1];
        out = (p & 1) ? (x1 * sn + x2 * c) : (x1 * c - x2 * sn);
    }
    row[d] = out;
}

// causal softmax with sink. Zero-fill (s, next 64-boundary) so PV gemm can K-cap.
__global__ __launch_bounds__(256) void softmax_k(const float* __restrict__ sink) {
    int s = blockIdx.x, h = blockIdx.y;
    float* row = g_scores + ((size_t)h * S_ + s) * S_;
    int L = s + 1;
    float snk = sink[h];
    float m = -3.4e38f;
    for (int t = threadIdx.x; t < L; t += 256) m = fmaxf(m, row[t] * SCALE_);
    m = block_reduce(m, true);
    m = fmaxf(m, snk);
    float sum = 0.f;
    for (int t = threadIdx.x; t < L; t += 256) sum += __expf(row[t] * SCALE_ - m);
    sum = block_reduce(sum, false);
    sum += __expf(snk - m);
    float inv = 1.f / sum;
    for (int t = threadIdx.x; t < L; t += 256) row[t] = __expf(row[t] * SCALE_ - m) * inv;
    int zend = min(S_, ((s >> 6) + 1) << 6);
    for (int t = L + threadIdx.x; t < zend; t += 256) row[t] = 0.f;
}

// inverse RoPE on last R dims of o
__global__ __launch_bounds__(64) void o_post() {
    int s = blockIdx.x, h = blockIdx.y;
    float* row = g_o + (size_t)s * (H_ * D_) + (size_t)h * D_ + NOPE_;
    __shared__ float sh[R_];
    int p = threadIdx.x;
    sh[p] = row[p];
    __syncthreads();
    int i = p >> 1;
    float c = g_cos[s * RH_ + i], sn = g_sin[s * RH_ + i];
    float x1 = sh[i << 1], x2 = sh[(i << 1) + 1];
    row[p] = (p & 1) ? (x2 * c - x1 * sn) : (x1 * c + x2 * sn);
}

// ---------------- launch ----------------
extern "C" void kernel_launch(void* const* d_in, const int* in_sizes, int n_in,
                              void* d_out, int out_size) {
    const float* x        = (const float*)d_in[0];
    const float* freqs    = (const float*)d_in[1];
    const float* wq_a     = (const float*)d_in[2];
    const float* q_norm_w = (const float*)d_in[3];
    const float* wq_b     = (const float*)d_in[4];
    const float* wkv      = (const float*)d_in[5];
    const float* kv_norm_w= (const float*)d_in[6];
    const float* wo_a_w   = (const float*)d_in[7];
    const float* wo_b     = (const float*)d_in[8];
    const float* sink     = (const float*)d_in[9];
    float* out = (float*)d_out;

    float *p_qa, *p_q, *p_kv, *p_sc, *p_o, *p_or;
    cudaGetSymbolAddress((void**)&p_qa, g_qa);
    cudaGetSymbolAddress((void**)&p_q,  g_q);
    cudaGetSymbolAddress((void**)&p_kv, g_kv);
    cudaGetSymbolAddress((void**)&p_sc, g_scores);
    cudaGetSymbolAddress((void**)&p_o,  g_o);
    cudaGetSymbolAddress((void**)&p_or, g_or);

    // cos/sin
    cos_sin_k<<<(S_ * RH_ + 255) / 256, 256>>>(freqs);

    // q_a = x @ wq_a^T   (2048 x 1024, K=2048)
    gemm_tn<<<dim3(QL_ / 64, S_ / 64, 1), 256>>>(x, wq_a, p_qa,
        HID_, HID_, HID_, QL_, 0, 0, 0, 0);
    rms_qa<<<S_, 256>>>(q_norm_w);

    // q = qa @ wq_b^T    (2048 x 4096, K=1024)
    gemm_tn<<<dim3((H_ * D_) / 64, S_ / 64, 1), 256>>>(p_qa, wq_b, p_q,
        QL_, QL_, QL_, H_ * D_, 0, 0, 0, 0);
    q_post<<<dim3(S_, H_), 256>>>();

    // kv = x @ wkv^T     (2048 x 256, K=2048)
    gemm_tn<<<dim3(D_ / 64, S_ / 64, 1), 256>>>(x, wkv, p_kv,
        HID_, HID_, HID_, D_, 0, 0, 0, 0);
    kv_post<<<S_, 256>>>(kv_norm_w);

    // scores[h] = q_h @ kv^T  (batched over 16 heads, causal block skip)
    gemm_tn<<<dim3(S_ / 64, S_ / 64, H_), 256>>>(p_q, p_kv, p_sc,
        D_, H_ * D_, D_, S_, (long)D_, 0, (long)S_ * S_, 1);

    // softmax with sink
    softmax_k<<<dim3(S_, H_), 256>>>(sink);

    // o[h] = probs[h] @ kv   (NN, K capped causally)
    gemm_nn<<<dim3(D_ / 64, S_ / 64, H_), 256>>>(p_sc, p_kv, p_o,
        S_, S_, D_, H_ * D_, (long)S_ * S_, 0, (long)D_, 1);

    // inverse RoPE on o_pe
    o_post<<<dim3(S_, H_), 64>>>();

    // grouped wo_a: batch G, A offset g*1024 within row, B rows offset g*512
    gemm_tn<<<dim3(OR_ / 64, S_ / 64, G_), 256>>>(p_o, wo_a_w, p_or,
        (H_ / G_) * D_, H_ * D_, (H_ / G_) * D_, G_ * OR_,
        (long)(H_ / G_) * D_, (long)OR_ * (H_ / G_) * D_, (long)OR_, 0);

    // out = o_r @ wo_b^T  (2048 x 2048, K=2048)
    gemm_tn<<<dim3(HID_ / 64, S_ / 64, 1), 256>>>(p_or, wo_b, out,
        G_ * OR_, G_ * OR_, G_ * OR_, HID_, 0, 0, 0, 0);
}

// round 3
// speedup vs baseline: 2.3356x; 2.3356x over previous
#include <cuda_runtime.h>
#include <cstdint>

#define S_    2048
#define HID_  2048
#define H_    16
#define D_    256
#define R_    64
#define RH_   32          // R/2
#define NOPE_ 192
#define QL_   1024
#define OR_   512
#define G_    4
#define EPS_  1e-6f
#define SCALE_ 0.0625f    // 256^-0.5

// ---------------- scratch (static device memory; allocation-free) ----------------
__device__ float g_cos[S_ * RH_];
__device__ float g_sin[S_ * RH_];
__device__ float g_qa[(size_t)S_ * QL_];          //  8 MB
__device__ float g_q[(size_t)S_ * H_ * D_];       // 32 MB
__device__ float g_kv[(size_t)S_ * D_];           //  2 MB
__device__ float g_scores[(size_t)H_ * S_ * S_];  // 256 MB
__device__ float g_o[(size_t)S_ * H_ * D_];       // 32 MB
__device__ float g_or[(size_t)S_ * G_ * OR_];     // 16 MB

// ---------------- helpers ----------------
__device__ __forceinline__ uint32_t f2tf(float x) {
    uint32_t r;
    asm("cvt.rna.tf32.f32 %0, %1;" : "=r"(r) : "f"(x));
    return r;
}

__device__ __forceinline__ void mma_tf32(float4& c, const uint32_t a[4], const uint32_t b[2]) {
    asm volatile(
        "mma.sync.aligned.m16n8k8.row.col.f32.tf32.tf32.f32 "
        "{%0,%1,%2,%3}, {%4,%5,%6,%7}, {%8,%9}, {%0,%1,%2,%3};\n"
        : "+f"(c.x), "+f"(c.y), "+f"(c.z), "+f"(c.w)
        : "r"(a[0]), "r"(a[1]), "r"(a[2]), "r"(a[3]), "r"(b[0]), "r"(b[1]));
}

__device__ __forceinline__ float block_reduce(float v, bool is_max) {
    __shared__ float warp_res[8];
    __shared__ float result;
    __syncthreads();
    #pragma unroll
    for (int o = 16; o; o >>= 1) {
        float other = __shfl_xor_sync(0xffffffffu, v, o);
        v = is_max ? fmaxf(v, other) : (v + other);
    }
    if ((threadIdx.x & 31) == 0) warp_res[threadIdx.x >> 5] = v;
    __syncthreads();
    if (threadIdx.x == 0) {
        int nw = (blockDim.x + 31) >> 5;
        float r = warp_res[0];
        for (int i = 1; i < nw; i++) r = is_max ? fmaxf(r, warp_res[i]) : (r + warp_res[i]);
        result = r;
    }
    __syncthreads();
    return result;
}

// ============================================================================
// TF32 tensor-core GEMM, TN:  C[M,N] = A[M,K] @ B[N,K]^T
// 128x128x16 block tile, 256 threads (8 warps, 2x4), 64x32 warp tile.
// Smem padded to 136 words/row -> conflict-free fragment loads.
// ============================================================================
__global__ __launch_bounds__(256) void gemm_tn_tc(
    const float* __restrict__ A, const float* __restrict__ B, float* __restrict__ C,
    int K, int lda, int ldb, int ldc,
    long sA, long sB, long sC, int causal_skip)
{
    int row0 = blockIdx.y * 128, col0 = blockIdx.x * 128;
    if (causal_skip && col0 > row0) return;
    A += (long)blockIdx.z * sA;
    B += (long)blockIdx.z * sB;
    C += (long)blockIdx.z * sC;

    __shared__ uint32_t As[16][136];
    __shared__ uint32_t Bs[16][136];

    int tid = threadIdx.x, lane = tid & 31, warp = tid >> 5;
    int wm = warp >> 2, wn = warp & 3;   // 2 x 4 warp grid

    float4 pa[2], pb[2];
    float4 c[4][4];
    #pragma unroll
    for (int i = 0; i < 4; i++)
        #pragma unroll
        for (int j = 0; j < 4; j++) c[i][j] = make_float4(0.f, 0.f, 0.f, 0.f);

    // prefetch first tile
    #pragma unroll
    for (int i = 0; i < 2; i++) {
        int f = tid + i * 256, r = f >> 2, kq = (f & 3) << 2;
        pa[i] = *(const float4*)(A + (long)(row0 + r) * lda + kq);
        pb[i] = *(const float4*)(B + (long)(col0 + r) * ldb + kq);
    }

    for (int k0 = 0; k0 < K; k0 += 16) {
        // store (with tf32 round) to shared, transposed to [k][m]
        #pragma unroll
        for (int i = 0; i < 2; i++) {
            int f = tid + i * 256, r = f >> 2, kq = (f & 3) << 2;
            As[kq + 0][r] = f2tf(pa[i].x); As[kq + 1][r] = f2tf(pa[i].y);
            As[kq + 2][r] = f2tf(pa[i].z); As[kq + 3][r] = f2tf(pa[i].w);
            Bs[kq + 0][r] = f2tf(pb[i].x); Bs[kq + 1][r] = f2tf(pb[i].y);
            Bs[kq + 2][r] = f2tf(pb[i].z); Bs[kq + 3][r] = f2tf(pb[i].w);
        }
        __syncthreads();
        if (k0 + 16 < K) {
            #pragma unroll
            for (int i = 0; i < 2; i++) {
                int f = tid + i * 256, r = f >> 2, kq = (f & 3) << 2;
                pa[i] = *(const float4*)(A + (long)(row0 + r) * lda + k0 + 16 + kq);
                pb[i] = *(const float4*)(B + (long)(col0 + r) * ldb + k0 + 16 + kq);
            }
        }
        #pragma unroll
        for (int ks = 0; ks < 2; ks++) {
            int lk = ks * 8 + (lane & 3);
            uint32_t af[4][4], bf[4][2];
            #pragma unroll
            for (int mt = 0; mt < 4; mt++) {
                int m = wm * 64 + mt * 16 + (lane >> 2);
                af[mt][0] = As[lk][m];     af[mt][1] = As[lk][m + 8];
                af[mt][2] = As[lk + 4][m]; af[mt][3] = As[lk + 4][m + 8];
            }
            #pragma unroll
            for (int nt = 0; nt < 4; nt++) {
                int n = wn * 32 + nt * 8 + (lane >> 2);
                bf[nt][0] = Bs[lk][n];
                bf[nt][1] = Bs[lk + 4][n];
            }
            #pragma unroll
            for (int mt = 0; mt < 4; mt++)
                #pragma unroll
                for (int nt = 0; nt < 4; nt++)
                    mma_tf32(c[mt][nt], af[mt], bf[nt]);
        }
        __syncthreads();
    }

    // epilogue
    #pragma unroll
    for (int mt = 0; mt < 4; mt++) {
        int m = row0 + wm * 64 + mt * 16 + (lane >> 2);
        #pragma unroll
        for (int nt = 0; nt < 4; nt++) {
            int n = col0 + wn * 32 + nt * 8 + ((lane & 3) << 1);
            *(float2*)(C + (long)m * ldc + n)       = make_float2(c[mt][nt].x, c[mt][nt].y);
            *(float2*)(C + (long)(m + 8) * ldc + n) = make_float2(c[mt][nt].z, c[mt][nt].w);
        }
    }
}

// ============================================================================
// TF32 tensor-core GEMM, NN:  C[M,N] = A[M,K] @ B[K,N]   (kcap for causal PV)
// ============================================================================
__global__ __launch_bounds__(256) void gemm_nn_tc(
    const float* __restrict__ A, const float* __restrict__ B, float* __restrict__ C,
    int K, int lda, int ldb, int ldc,
    long sA, long sB, long sC, int kcap)
{
    int row0 = blockIdx.y * 128, col0 = blockIdx.x * 128;
    A += (long)blockIdx.z * sA;
    B += (long)blockIdx.z * sB;
    C += (long)blockIdx.z * sC;

    int Keff = kcap ? min(K, row0 + 128) : K;

    __shared__ uint32_t As[16][136];
    __shared__ uint32_t Bs[16][136];

    int tid = threadIdx.x, lane = tid & 31, warp = tid >> 5;
    int wm = warp >> 2, wn = warp & 3;

    float4 pa[2], pb[2];
    float4 c[4][4];
    #pragma unroll
    for (int i = 0; i < 4; i++)
        #pragma unroll
        for (int j = 0; j < 4; j++) c[i][j] = make_float4(0.f, 0.f, 0.f, 0.f);

    #pragma unroll
    for (int i = 0; i < 2; i++) {
        int f = tid + i * 256;
        int ar = f >> 2, akq = (f & 3) << 2;
        pa[i] = *(const float4*)(A + (long)(row0 + ar) * lda + akq);
        int bk = f >> 5, bnq = (f & 31) << 2;
        pb[i] = *(const float4*)(B + (long)bk * ldb + col0 + bnq);
    }

    for (int k0 = 0; k0 < Keff; k0 += 16) {
        #pragma unroll
        for (int i = 0; i < 2; i++) {
            int f = tid + i * 256;
            int ar = f >> 2, akq = (f & 3) << 2;
            As[akq + 0][ar] = f2tf(pa[i].x); As[akq + 1][ar] = f2tf(pa[i].y);
            As[akq + 2][ar] = f2tf(pa[i].z); As[akq + 3][ar] = f2tf(pa[i].w);
            int bk = f >> 5, bnq = (f & 31) << 2;
            Bs[bk][bnq + 0] = f2tf(pb[i].x); Bs[bk][bnq + 1] = f2tf(pb[i].y);
            Bs[bk][bnq + 2] = f2tf(pb[i].z); Bs[bk][bnq + 3] = f2tf(pb[i].w);
        }
        __syncthreads();
        if (k0 + 16 < Keff) {
            #pragma unroll
            for (int i = 0; i < 2; i++) {
                int f = tid + i * 256;
                int ar = f >> 2, akq = (f & 3) << 2;
                pa[i] = *(const float4*)(A + (long)(row0 + ar) * lda + k0 + 16 + akq);
                int bk = f >> 5, bnq = (f & 31) << 2;
                pb[i] = *(const float4*)(B + (long)(k0 + 16 + bk) * ldb + col0 + bnq);
            }
        }
        #pragma unroll
        for (int ks = 0; ks < 2; ks++) {
            int lk = ks * 8 + (lane & 3);
            uint32_t af[4][4], bf[4][2];
            #pragma unroll
            for (int mt = 0; mt < 4; mt++) {
                int m = wm * 64 + mt * 16 + (lane >> 2);
                af[mt][0] = As[lk][m];     af[mt][1] = As[lk][m + 8];
                af[mt][2] = As[lk + 4][m]; af[mt][3] = As[lk + 4][m + 8];
            }
            #pragma unroll
            for (int nt = 0; nt < 4; nt++) {
                int n = wn * 32 + nt * 8 + (lane >> 2);
                bf[nt][0] = Bs[lk][n];
                bf[nt][1] = Bs[lk + 4][n];
            }
            #pragma unroll
            for (int mt = 0; mt < 4; mt++)
                #pragma unroll
                for (int nt = 0; nt < 4; nt++)
                    mma_tf32(c[mt][nt], af[mt], bf[nt]);
        }
        __syncthreads();
    }

    #pragma unroll
    for (int mt = 0; mt < 4; mt++) {
        int m = row0 + wm * 64 + mt * 16 + (lane >> 2);
        #pragma unroll
        for (int nt = 0; nt < 4; nt++) {
            int n = col0 + wn * 32 + nt * 8 + ((lane & 3) << 1);
            *(float2*)(C + (long)m * ldc + n)       = make_float2(c[mt][nt].x, c[mt][nt].y);
            *(float2*)(C + (long)(m + 8) * ldc + n) = make_float2(c[mt][nt].z, c[mt][nt].w);
        }
    }
}

// ---------------- elementwise / norm kernels ----------------
__global__ void cos_sin_k(const float* __restrict__ freqs) {
    int i = blockIdx.x * blockDim.x + threadIdx.x;
    if (i < S_ * RH_) {
        float f = freqs[i];
        g_cos[i] = cosf(f);
        g_sin[i] = sinf(f);
    }
}

__global__ __launch_bounds__(256) void rms_qa(const float* __restrict__ w) {
    int s = blockIdx.x;
    float* row = g_qa + (long)s * QL_;
    float ss = 0.f;
    for (int i = threadIdx.x; i < QL_; i += 256) { float v = row[i]; ss += v * v; }
    ss = block_reduce(ss, false);
    float sc = rsqrtf(ss / QL_ + EPS_);
    for (int i = threadIdx.x; i < QL_; i += 256) row[i] = row[i] * sc * w[i];
}

__global__ __launch_bounds__(256) void q_post() {
    int s = blockIdx.x, h = blockIdx.y;
    float* row = g_q + (size_t)s * (H_ * D_) + (size_t)h * D_;
    int d = threadIdx.x;
    float v = row[d];
    float ss = block_reduce(v * v, false);
    float sc = rsqrtf(ss / D_ + EPS_);
    __shared__ float sh[D_];
    sh[d] = v * sc;
    __syncthreads();
    float out;
    if (d < NOPE_) out = sh[d];
    else {
        int p = d - NOPE_, i = p >> 1;
        float cc = g_cos[s * RH_ + i], sn = g_sin[s * RH_ + i];
        float x1 = sh[NOPE_ + (i << 1)], x2 = sh[NOPE_ + (i << 1) + 1];
        out = (p & 1) ? (x1 * sn + x2 * cc) : (x1 * cc - x2 * sn);
    }
    row[d] = out;
}

__global__ __launch_bounds__(256) void kv_post(const float* __restrict__ w) {
    int s = blockIdx.x;
    float* row = g_kv + (long)s * D_;
    int d = threadIdx.x;
    float v = row[d];
    float ss = block_reduce(v * v, false);
    float sc = rsqrtf(ss / D_ + EPS_);
    __shared__ float sh[D_];
    sh[d] = v * sc * w[d];
    __syncthreads();
    float out;
    if (d < NOPE_) out = sh[d];
    else {
        int p = d - NOPE_, i = p >> 1;
        float cc = g_cos[s * RH_ + i], sn = g_sin[s * RH_ + i];
        float x1 = sh[NOPE_ + (i << 1)], x2 = sh[NOPE_ + (i << 1) + 1];
        out = (p & 1) ? (x1 * sn + x2 * cc) : (x1 * cc - x2 * sn);
    }
    row[d] = out;
}

// causal softmax with sink. Zero-fill up to the 128-boundary for the K-capped PV GEMM.
__global__ __launch_bounds__(256) void softmax_k(const float* __restrict__ sink) {
    int s = blockIdx.x, h = blockIdx.y;
    float* row = g_scores + ((size_t)h * S_ + s) * S_;
    int L = s + 1;
    float snk = sink[h];
    float m = -3.4e38f;
    for (int t = threadIdx.x; t < L; t += 256) m = fmaxf(m, row[t] * SCALE_);
    m = block_reduce(m, true);
    m = fmaxf(m, snk);
    float sum = 0.f;
    for (int t = threadIdx.x; t < L; t += 256) sum += __expf(row[t] * SCALE_ - m);
    sum = block_reduce(sum, false);
    sum += __expf(snk - m);
    float inv = 1.f / sum;
    for (int t = threadIdx.x; t < L; t += 256) row[t] = __expf(row[t] * SCALE_ - m) * inv;
    int zend = min(S_, ((s >> 7) + 1) << 7);
    for (int t = L + threadIdx.x; t < zend; t += 256) row[t] = 0.f;
}

__global__ __launch_bounds__(64) void o_post() {
    int s = blockIdx.x, h = blockIdx.y;
    float* row = g_o + (size_t)s * (H_ * D_) + (size_t)h * D_ + NOPE_;
    __shared__ float sh[R_];
    int p = threadIdx.x;
    sh[p] = row[p];
    __syncthreads();
    int i = p >> 1;
    float cc = g_cos[s * RH_ + i], sn = g_sin[s * RH_ + i];
    float x1 = sh[i << 1], x2 = sh[(i << 1) + 1];
    row[p] = (p & 1) ? (x2 * cc - x1 * sn) : (x1 * cc + x2 * sn);
}

// ---------------- launch ----------------
extern "C" void kernel_launch(void* const* d_in, const int* in_sizes, int n_in,
                              void* d_out, int out_size) {
    const float* x        = (const float*)d_in[0];
    const float* freqs    = (const float*)d_in[1];
    const float* wq_a     = (const float*)d_in[2];
    const float* q_norm_w = (const float*)d_in[3];
    const float* wq_b     = (const float*)d_in[4];
    const float* wkv      = (const float*)d_in[5];
    const float* kv_norm_w= (const float*)d_in[6];
    const float* wo_a_w   = (const float*)d_in[7];
    const float* wo_b     = (const float*)d_in[8];
    const float* sink     = (const float*)d_in[9];
    float* out = (float*)d_out;

    float *p_qa, *p_q, *p_kv, *p_sc, *p_o, *p_or;
    cudaGetSymbolAddress((void**)&p_qa, g_qa);
    cudaGetSymbolAddress((void**)&p_q,  g_q);
    cudaGetSymbolAddress((void**)&p_kv, g_kv);
    cudaGetSymbolAddress((void**)&p_sc, g_scores);
    cudaGetSymbolAddress((void**)&p_o,  g_o);
    cudaGetSymbolAddress((void**)&p_or, g_or);

    cos_sin_k<<<(S_ * RH_ + 255) / 256, 256>>>(freqs);

    // q_a = x @ wq_a^T   (2048 x 1024, K=2048)
    gemm_tn_tc<<<dim3(QL_ / 128, S_ / 128, 1), 256>>>(x, wq_a, p_qa,
        HID_, HID_, HID_, QL_, 0, 0, 0, 0);
    rms_qa<<<S_, 256>>>(q_norm_w);

    // q = qa @ wq_b^T    (2048 x 4096, K=1024)
    gemm_tn_tc<<<dim3((H_ * D_) / 128, S_ / 128, 1), 256>>>(p_qa, wq_b, p_q,
        QL_, QL_, QL_, H_ * D_, 0, 0, 0, 0);
    q_post<<<dim3(S_, H_), 256>>>();

    // kv = x @ wkv^T     (2048 x 256, K=2048)
    gemm_tn_tc<<<dim3(D_ / 128, S_ / 128, 1), 256>>>(x, wkv, p_kv,
        HID_, HID_, HID_, D_, 0, 0, 0, 0);
    kv_post<<<S_, 256>>>(kv_norm_w);

    // scores[h] = q_h @ kv^T  (batched over 16 heads, causal block skip)
    gemm_tn_tc<<<dim3(S_ / 128, S_ / 128, H_), 256>>>(p_q, p_kv, p_sc,
        D_, H_ * D_, D_, S_, (long)D_, 0, (long)S_ * S_, 1);

    softmax_k<<<dim3(S_, H_), 256>>>(sink);

    // o[h] = probs[h] @ kv   (NN, K capped causally)
    gemm_nn_tc<<<dim3(D_ / 128, S_ / 128, H_), 256>>>(p_sc, p_kv, p_o,
        S_, S_, D_, H_ * D_, (long)S_ * S_, 0, (long)D_, 1);

    o_post<<<dim3(S_, H_), 64>>>();

    // grouped wo_a: batch G
    gemm_tn_tc<<<dim3(OR_ / 128, S_ / 128, G_), 256>>>(p_o, wo_a_w, p_or,
        (H_ / G_) * D_, H_ * D_, (H_ / G_) * D_, G_ * OR_,
        (long)(H_ / G_) * D_, (long)OR_ * (H_ / G_) * D_, (long)OR_, 0);

    // out = o_r @ wo_b^T  (2048 x 2048, K=2048)
    gemm_tn_tc<<<dim3(HID_ / 128, S_ / 128, 1), 256>>>(p_or, wo_b, out,
        G_ * OR_, G_ * OR_, G_ * OR_, HID_, 0, 0, 0, 0);
}